// round 15
// baseline (speedup 1.0000x reference)
#include <cuda_runtime.h>
#include <cuda_bf16.h>

// ---------------------------------------------------------------------------
// BaseGNN: 3-layer GCN, N=100000, E=1.6M, B=64. Persistent mega-kernel.
// R14: 541us (DRAM 2.2% -> L2 resident; issue 28% latency-bound, regs=64 pin
// 4 CTAs/SM). R15: occupancy push to 6 CTAs/SM (launch_bounds(256,6), 42 regs,
// 888 blocks) — bf16 staging halved agg register needs, making 42 feasible.
// 8 even grid barriers (sense self-resets per graph replay).
// ---------------------------------------------------------------------------

#define N_MAX 100000
#define E_MAX 1600000
#define NB    64
#define HID   128
#define OUTD  256
#define NBLK  888
#define NTHR  256
#define NWARP (NBLK * 8)

__device__ int   g_deg[N_MAX];
__device__ int   g_rowptr[N_MAX + 1];
__device__ int   g_cursor[N_MAX];
__device__ int2  g_edge[E_MAX];          // {src, float-bits(norm)}
__device__ __nv_bfloat16 g_bufA[(size_t)N_MAX * HID];
__device__ __nv_bfloat16 g_res [(size_t)N_MAX * HID];
__device__ __nv_bfloat16 g_hbuf[(size_t)N_MAX * HID];
__device__ float g_pool[NB * HID];
__device__ int   g_cnt[NB];
__device__ unsigned g_bar_count = 0;
__device__ unsigned g_bar_sense = 0;

__device__ __forceinline__ void grid_barrier(unsigned& ls) {
    __threadfence();
    __syncthreads();
    ls ^= 1u;
    if (threadIdx.x == 0) {
        unsigned arrived = atomicAdd(&g_bar_count, 1u);
        if (arrived == NBLK - 1u) {
            atomicExch(&g_bar_count, 0u);
            __threadfence();
            atomicExch(&g_bar_sense, ls);
        } else {
            while (((volatile unsigned*)&g_bar_sense)[0] != ls) __nanosleep(64);
            __threadfence();
        }
    }
    __syncthreads();
}

// ---------------------------------------------------------------------------
// L2 residency policy helpers + bf16 packed load/store.
__device__ __forceinline__ unsigned long long mk_policy() {
    unsigned long long p;
    asm("createpolicy.fractional.L2::evict_last.b64 %0, 1.0;" : "=l"(p));
    return p;
}
// load 4 bf16 (8B) -> float4, with evict_last policy
__device__ __forceinline__ float4 ldg_bf4(const __nv_bfloat16* p, unsigned long long pol) {
    unsigned lo, hi;
    asm volatile("ld.global.L2::cache_hint.v2.u32 {%0,%1}, [%2], %3;"
                 : "=r"(lo), "=r"(hi) : "l"(p), "l"(pol));
    __nv_bfloat162 b0 = *reinterpret_cast<__nv_bfloat162*>(&lo);
    __nv_bfloat162 b1 = *reinterpret_cast<__nv_bfloat162*>(&hi);
    float2 f0 = __bfloat1622float2(b0);
    float2 f1 = __bfloat1622float2(b1);
    return make_float4(f0.x, f0.y, f1.x, f1.y);
}
__device__ __forceinline__ void stg_bf4(__nv_bfloat16* p, float4 v, unsigned long long pol) {
    __nv_bfloat162 b0 = __floats2bfloat162_rn(v.x, v.y);
    __nv_bfloat162 b1 = __floats2bfloat162_rn(v.z, v.w);
    unsigned lo = *reinterpret_cast<unsigned*>(&b0);
    unsigned hi = *reinterpret_cast<unsigned*>(&b1);
    asm volatile("st.global.L2::cache_hint.v2.u32 [%0], {%1,%2}, %3;"
                 :: "l"(p), "r"(lo), "r"(hi), "l"(pol) : "memory");
}
__device__ __forceinline__ void stg_bf2(__nv_bfloat16* p, float a, float b, unsigned long long pol) {
    __nv_bfloat162 bb = __floats2bfloat162_rn(a, b);
    unsigned u = *reinterpret_cast<unsigned*>(&bb);
    asm volatile("st.global.L2::cache_hint.b32 [%0], %1, %2;"
                 :: "l"(p), "r"(u), "l"(pol) : "memory");
}

__device__ __forceinline__ void fma4(float4& acc, const float4& a, float w) {
    acc.x += a.x * w; acc.y += a.y * w; acc.z += a.z * w; acc.w += a.w * w;
}

// ---------------------------------------------------------------------------
// Process one node's edge list; first-group records already in `rec`.
__device__ __forceinline__ void gather_body(const __nv_bfloat16* __restrict__ h, int lane,
                                            int2 rec, int start, int end, float4& acc,
                                            unsigned long long pol) {
    for (int e0 = start; e0 < end; e0 += 32) {
        if (e0 != start) {               // reload for rare deg>32 nodes
            int e = e0 + lane;
            rec = (e < end) ? g_edge[e] : make_int2(0, 0);
        }
        int cnt = min(32, end - e0);
        int j = 0;
        for (; j + 8 <= cnt; j += 8) {
            int   s[8]; float w[8]; float4 a[8];
            #pragma unroll
            for (int q = 0; q < 8; q++) {
                s[q] = __shfl_sync(0xffffffffu, rec.x, j + q);
                w[q] = __int_as_float(__shfl_sync(0xffffffffu, rec.y, j + q));
            }
            #pragma unroll
            for (int q = 0; q < 8; q++) a[q] = ldg_bf4(h + (size_t)s[q] * HID + lane * 4, pol);
            #pragma unroll
            for (int q = 0; q < 8; q++) fma4(acc, a[q], w[q]);
        }
        for (; j + 4 <= cnt; j += 4) {
            int   s[4]; float w[4]; float4 a[4];
            #pragma unroll
            for (int q = 0; q < 4; q++) {
                s[q] = __shfl_sync(0xffffffffu, rec.x, j + q);
                w[q] = __int_as_float(__shfl_sync(0xffffffffu, rec.y, j + q));
            }
            #pragma unroll
            for (int q = 0; q < 4; q++) a[q] = ldg_bf4(h + (size_t)s[q] * HID + lane * 4, pol);
            #pragma unroll
            for (int q = 0; q < 4; q++) fma4(acc, a[q], w[q]);
        }
        for (; j < cnt; j++) {
            int   ss = __shfl_sync(0xffffffffu, rec.x, j);
            float ww = __int_as_float(__shfl_sync(0xffffffffu, rec.y, j));
            float4 a0 = ldg_bf4(h + (size_t)ss * HID + lane * 4, pol);
            fma4(acc, a0, ww);
        }
    }
}

// bias + residual + LN + ReLU epilogue, then bf16 store.
__device__ __forceinline__ void ln_store(float4 acc, float4 rr,
                                         const float* __restrict__ bias,
                                         const float* __restrict__ gam,
                                         const float* __restrict__ bet,
                                         __nv_bfloat16* __restrict__ outp, int node, int lane,
                                         unsigned long long pol) {
    float4 b4 = ((const float4*)bias)[lane];
    acc.x += rr.x + b4.x; acc.y += rr.y + b4.y;
    acc.z += rr.z + b4.z; acc.w += rr.w + b4.w;
    float s  = acc.x + acc.y + acc.z + acc.w;
    float sq = acc.x*acc.x + acc.y*acc.y + acc.z*acc.z + acc.w*acc.w;
    #pragma unroll
    for (int off = 16; off > 0; off >>= 1) {
        s  += __shfl_xor_sync(0xffffffffu, s,  off);
        sq += __shfl_xor_sync(0xffffffffu, sq, off);
    }
    float mu  = s * (1.f / HID);
    float var = sq * (1.f / HID) - mu * mu;
    float rs  = rsqrtf(var + 1e-5f);
    float4 g4 = ((const float4*)gam)[lane];
    float4 l4 = ((const float4*)bet)[lane];
    float4 o;
    o.x = fmaxf(0.f, (acc.x - mu) * rs * g4.x + l4.x);
    o.y = fmaxf(0.f, (acc.y - mu) * rs * g4.y + l4.y);
    o.z = fmaxf(0.f, (acc.z - mu) * rs * g4.z + l4.z);
    o.w = fmaxf(0.f, (acc.w - mu) * rs * g4.w + l4.w);
    stg_bf4(outp + (size_t)node * HID + lane * 4, o, pol);
}

// Aggregate + LN phase, software-pipelined across strided nodes.
// RESID_X: residual recomputed as x@rW+rb (rW/rb in sW smem); else bf16 rbuf.
template<bool RESID_X>
__device__ void agg_ln_phase(const __nv_bfloat16* __restrict__ h,
                             const float* __restrict__ xsrc,
                             const __nv_bfloat16* __restrict__ rbuf,
                             const float* __restrict__ bias, const float* __restrict__ gam,
                             const float* __restrict__ bet, __nv_bfloat16* __restrict__ outp,
                             int n, int gwarp, int lane, const float* sW,
                             unsigned long long pol) {
    int node = gwarp;
    if (node >= n) return;
    int start = g_rowptr[node], end = g_rowptr[node + 1];
    int2 rec = (start + lane < end) ? g_edge[start + lane] : make_int2(0, 0);
    float4 self = ldg_bf4(h + (size_t)node * HID + lane * 4, pol);
    float xv = 0.f;
    if (RESID_X) xv = (lane < 20) ? xsrc[(size_t)node * 20 + lane] : 0.f;
    while (true) {
        int nxt = node + NWARP;
        bool has = nxt < n;
        int s2 = 0, e2 = 0;
        int2 rec2 = make_int2(0, 0);
        float4 self2 = make_float4(0.f, 0.f, 0.f, 0.f);
        float xv2 = 0.f;
        if (has) {                               // prefetch next node
            s2 = g_rowptr[nxt]; e2 = g_rowptr[nxt + 1];
            rec2 = (s2 + lane < e2) ? g_edge[s2 + lane] : make_int2(0, 0);
            self2 = ldg_bf4(h + (size_t)nxt * HID + lane * 4, pol);
            if (RESID_X) xv2 = (lane < 20) ? xsrc[(size_t)nxt * 20 + lane] : 0.f;
        }
        float wl = 1.f / (float)(end - start + 1);   // deg+1 (self loop)
        float4 acc = make_float4(self.x * wl, self.y * wl, self.z * wl, self.w * wl);
        gather_body(h, lane, rec, start, end, acc, pol);
        float4 rr;
        if (RESID_X) {
            rr = ((const float4*)(sW + 20 * 128))[lane];   // rb
            #pragma unroll
            for (int k = 0; k < 20; k++) {
                float xk = __shfl_sync(0xffffffffu, xv, k);
                float4 w = ((const float4*)(sW + k * 128))[lane];
                fma4(rr, w, xk);
            }
        } else {
            rr = ldg_bf4(rbuf + (size_t)node * HID + lane * 4, pol);
        }
        ln_store(acc, rr, bias, gam, bet, outp, node, lane, pol);
        if (!has) break;
        node = nxt; start = s2; end = e2; rec = rec2; self = self2; xv = xv2;
    }
}

// ---------------------------------------------------------------------------
// tf32 helpers
__device__ __forceinline__ unsigned f2tf(float f) {
    unsigned r;
    asm("cvt.rna.tf32.f32 %0, %1;" : "=r"(r) : "f"(f));
    return r;
}
__device__ __forceinline__ void mma_tf32(float& d0, float& d1, float& d2, float& d3,
                                         unsigned a0, unsigned a1, unsigned a2, unsigned a3,
                                         unsigned b0, unsigned b1) {
    asm volatile(
        "mma.sync.aligned.m16n8k8.row.col.f32.tf32.tf32.f32 "
        "{%0,%1,%2,%3}, {%4,%5,%6,%7}, {%8,%9}, {%0,%1,%2,%3};\n"
        : "+f"(d0), "+f"(d1), "+f"(d2), "+f"(d3)
        : "r"(a0), "r"(a1), "r"(a2), "r"(a3), "r"(b0), "r"(b1));
}

// GEMM phase: C[n,128] = A_bf16[n,128] @ W[128,128]; 64x64 tiles, tf32 MMA.
// bf16 -> fp32 -> tf32 is exact. Output stored bf16 with evict_last.
__device__ void gemm_phase128(const __nv_bfloat16* __restrict__ A, const float* __restrict__ W,
                              __nv_bfloat16* __restrict__ C, int n, float* sh,
                              unsigned long long pol) {
    const int rowTiles = (n + 63) >> 6;
    const int ntiles = rowTiles * 2;
    float (*As)[68] = (float(*)[68])sh;              // [32][68] (k-major)
    float (*Ws)[64] = (float(*)[64])(sh + 32 * 68);  // [32][64]
    int tid = threadIdx.x;
    int lane = tid & 31, wid = tid >> 5;
    int wr = (wid & 3) * 16;
    int wc = (wid >> 2) * 32;
    int frow = lane >> 2;
    int fcol = lane & 3;
    for (int t = blockIdx.x; t < ntiles; t += NBLK) {
        int row0 = (t % rowTiles) << 6;
        int col0 = (t / rowTiles) << 6;
        float d[4][4];
        #pragma unroll
        for (int nt = 0; nt < 4; nt++)
            #pragma unroll
            for (int q = 0; q < 4; q++) d[nt][q] = 0.f;
        #pragma unroll
        for (int k0 = 0; k0 < 128; k0 += 32) {
            #pragma unroll
            for (int l = tid; l < 64 * 8; l += NTHR) {
                int m = l >> 3, k4 = l & 7;
                int r = row0 + m;
                float4 v = (r < n) ? ldg_bf4(A + (size_t)r * 128 + k0 + k4 * 4, pol)
                                   : make_float4(0.f, 0.f, 0.f, 0.f);
                As[k4 * 4 + 0][m] = v.x;
                As[k4 * 4 + 1][m] = v.y;
                As[k4 * 4 + 2][m] = v.z;
                As[k4 * 4 + 3][m] = v.w;
            }
            #pragma unroll
            for (int l = tid; l < 32 * 16; l += NTHR) {
                int k = l >> 4, c4 = l & 15;
                float4 v = ((const float4*)(W + (size_t)(k0 + k) * 128 + col0))[c4];
                ((float4*)&Ws[k][c4 * 4])[0] = v;
            }
            __syncthreads();
            #pragma unroll
            for (int kk = 0; kk < 32; kk += 8) {
                int ak = kk + fcol;
                int ar = wr + frow;
                unsigned a0 = f2tf(As[ak    ][ar    ]);
                unsigned a1 = f2tf(As[ak    ][ar + 8]);
                unsigned a2 = f2tf(As[ak + 4][ar    ]);
                unsigned a3 = f2tf(As[ak + 4][ar + 8]);
                #pragma unroll
                for (int nt = 0; nt < 4; nt++) {
                    int bc = wc + nt * 8 + frow;
                    unsigned b0 = f2tf(Ws[ak    ][bc]);
                    unsigned b1 = f2tf(Ws[ak + 4][bc]);
                    mma_tf32(d[nt][0], d[nt][1], d[nt][2], d[nt][3],
                             a0, a1, a2, a3, b0, b1);
                }
            }
            __syncthreads();
        }
        int r = row0 + wr + frow;
        #pragma unroll
        for (int nt = 0; nt < 4; nt++) {
            int c = col0 + wc + nt * 8 + fcol * 2;
            if (r < n)     stg_bf2(C + (size_t)r * 128 + c,       d[nt][0], d[nt][1], pol);
            if (r + 8 < n) stg_bf2(C + (size_t)(r + 8) * 128 + c, d[nt][2], d[nt][3], pol);
        }
    }
}

// ---------------------------------------------------------------------------
__global__ void __launch_bounds__(NTHR, 6) mega_kernel(
    const float* __restrict__ x, const int* __restrict__ src,
    const int* __restrict__ dst, const int* __restrict__ batch,
    const float* __restrict__ W1, const float* __restrict__ b1,
    const float* __restrict__ W2, const float* __restrict__ b2,
    const float* __restrict__ W3, const float* __restrict__ b3,
    const float* __restrict__ rW, const float* __restrict__ rb,
    const float* __restrict__ g1, const float* __restrict__ be1,
    const float* __restrict__ g2, const float* __restrict__ be2,
    float* __restrict__ out, int n, int e)
{
    __shared__ float sh[5248];
    unsigned ls = 0;
    const unsigned long long pol = mk_policy();
    const int tid  = threadIdx.x;
    const int gtid = blockIdx.x * NTHR + tid;
    const int gstr = NBLK * NTHR;
    const int lane = tid & 31, wid = tid >> 5;
    const int gwarp = blockIdx.x * 8 + wid;

    // ---- P0: zero ----
    for (int i = gtid; i < n; i += gstr) g_deg[i] = 0;
    if (gtid < NB) g_cnt[gtid] = 0;
    for (int i = gtid; i < NB * HID; i += gstr) g_pool[i] = 0.f;
    grid_barrier(ls);                                            // B1

    // ---- P1: histograms ----
    for (int i = gtid; i < e; i += gstr) atomicAdd(&g_deg[dst[i]], 1);
    for (int i = gtid; i < n; i += gstr) atomicAdd(&g_cnt[batch[i]], 1);
    grid_barrier(ls);                                            // B2

    // ---- P2: block 0 scans (4 elems/thread); others do the W1 input GEMM ----
    if (blockIdx.x == 0) {
        int* wsum = (int*)sh;
        int carry = 0;
        for (int base = 0; base < n; base += NTHR * 4) {
            int i0 = base + tid * 4;
            int v0 = (i0 + 0 < n) ? g_deg[i0 + 0] : 0;
            int v1 = (i0 + 1 < n) ? g_deg[i0 + 1] : 0;
            int v2 = (i0 + 2 < n) ? g_deg[i0 + 2] : 0;
            int v3 = (i0 + 3 < n) ? g_deg[i0 + 3] : 0;
            int tsum = v0 + v1 + v2 + v3;
            int xv = tsum;
            #pragma unroll
            for (int off = 1; off < 32; off <<= 1) {
                int t = __shfl_up_sync(0xffffffffu, xv, off);
                if (lane >= off) xv += t;
            }
            if (lane == 31) wsum[wid] = xv;
            __syncthreads();
            if (wid == 0) {
                int sv = (lane < 8) ? wsum[lane] : 0;
                #pragma unroll
                for (int off = 1; off < 8; off <<= 1) {
                    int t = __shfl_up_sync(0xffffffffu, sv, off);
                    if (lane >= off) sv += t;
                }
                if (lane < 8) wsum[lane] = sv;
            }
            __syncthreads();
            int excl = carry + (wid ? wsum[wid - 1] : 0) + xv - tsum;
            if (i0 + 0 < n) { g_rowptr[i0 + 0] = excl;                g_cursor[i0 + 0] = excl; }
            if (i0 + 1 < n) { g_rowptr[i0 + 1] = excl + v0;           g_cursor[i0 + 1] = excl + v0; }
            if (i0 + 2 < n) { g_rowptr[i0 + 2] = excl + v0 + v1;      g_cursor[i0 + 2] = excl + v0 + v1; }
            if (i0 + 3 < n) { g_rowptr[i0 + 3] = excl + v0 + v1 + v2; g_cursor[i0 + 3] = excl + v0 + v1 + v2; }
            int total = wsum[7];
            __syncthreads();
            carry += total;
        }
        if (tid == 0) g_rowptr[n] = carry;
    } else {
        float* sW1 = sh;            // 2560 floats
        for (int i = tid; i < 20 * 128; i += NTHR) sW1[i] = W1[i];
        __syncthreads();
        int w2 = (blockIdx.x - 1) * 8 + wid;
        for (int row = w2; row < n; row += (NBLK - 1) * 8) {
            float xv = (lane < 20) ? x[(size_t)row * 20 + lane] : 0.f;
            float4 a = make_float4(0.f, 0.f, 0.f, 0.f);
            #pragma unroll
            for (int k = 0; k < 20; k++) {
                float xk = __shfl_sync(0xffffffffu, xv, k);
                float4 w = ((const float4*)(sW1 + k * 128))[lane];
                fma4(a, w, xk);
            }
            stg_bf4(g_bufA + (size_t)row * HID + lane * 4, a, pol);
        }
    }
    grid_barrier(ls);                                            // B3

    // ---- P3: csr fill ----
    for (int i = gtid; i < e; i += gstr) {
        int s = src[i], d = dst[i];
        int pos = atomicAdd(&g_cursor[d], 1);
        float nrm = rsqrtf((float)(g_deg[s] + 1) * (float)(g_deg[d] + 1));
        g_edge[pos] = make_int2(s, __float_as_int(nrm));
    }
    grid_barrier(ls);                                            // B4

    // ---- layer 1: aggregate + (x@rW+rb) residual + bias + LN + ReLU ----
    {
        for (int i = tid; i < 20 * 128; i += NTHR) sh[i] = rW[i];
        if (tid < 128) sh[20 * 128 + tid] = rb[tid];
        __syncthreads();
        agg_ln_phase<true>(g_bufA, x, nullptr, b1, g1, be1, g_hbuf, n, gwarp, lane, sh, pol);
    }
    grid_barrier(ls);                                            // B5

    // ---- layer 2 GEMM (tf32 MMA, bf16 in/out, evict_last) ----
    gemm_phase128(g_hbuf, W2, g_bufA, n, sh, pol);
    grid_barrier(ls);                                            // B6

    agg_ln_phase<false>(g_bufA, nullptr, g_hbuf, b2, g2, be2, g_res, n, gwarp, lane, nullptr, pol);
    grid_barrier(ls);                                            // B7

    // ---- layer 3: aggregate + pool fused (contiguous chunks, pipelined) ----
    {
        int ch = (n + NWARP - 1) / NWARP;
        int lo = gwarp * ch;
        int hi = min(n, lo + ch);
        if (lo < hi) {
            float4 pacc = make_float4(0.f, 0.f, 0.f, 0.f);
            int cur = batch[lo];
            int node = lo;
            int start = g_rowptr[node], end = g_rowptr[node + 1];
            int2 rec = (start + lane < end) ? g_edge[start + lane] : make_int2(0, 0);
            float4 self = ldg_bf4(g_res + (size_t)node * HID + lane * 4, pol);
            while (true) {
                int nxt = node + 1;
                bool has = nxt < hi;
                int s2 = 0, e2 = 0;
                int2 rec2 = make_int2(0, 0);
                float4 self2 = make_float4(0.f, 0.f, 0.f, 0.f);
                int gnxt = cur;
                if (has) {
                    s2 = g_rowptr[nxt]; e2 = g_rowptr[nxt + 1];
                    rec2 = (s2 + lane < e2) ? g_edge[s2 + lane] : make_int2(0, 0);
                    self2 = ldg_bf4(g_res + (size_t)nxt * HID + lane * 4, pol);
                    gnxt = batch[nxt];
                }
                float wl = 1.f / (float)(end - start + 1);
                float4 acc = make_float4(self.x * wl, self.y * wl, self.z * wl, self.w * wl);
                gather_body(g_res, lane, rec, start, end, acc, pol);
                pacc.x += acc.x; pacc.y += acc.y; pacc.z += acc.z; pacc.w += acc.w;
                if (!has) break;
                if (gnxt != cur) {
                    float* p = &g_pool[cur * HID + lane * 4];
                    atomicAdd(p + 0, pacc.x); atomicAdd(p + 1, pacc.y);
                    atomicAdd(p + 2, pacc.z); atomicAdd(p + 3, pacc.w);
                    pacc = make_float4(0.f, 0.f, 0.f, 0.f);
                    cur = gnxt;
                }
                node = nxt; start = s2; end = e2; rec = rec2; self = self2;
            }
            float* p = &g_pool[cur * HID + lane * 4];
            atomicAdd(p + 0, pacc.x); atomicAdd(p + 1, pacc.y);
            atomicAdd(p + 2, pacc.z); atomicAdd(p + 3, pacc.w);
        }
    }
    grid_barrier(ls);                                            // B8 (even count)

    // ---- final: out[b,:] = (pool[b,:]/cnt[b]) @ W3 + b3 (blocks 0..63) ----
    if (blockIdx.x < NB) {
        int b = blockIdx.x;
        float* sp = sh;               // 128 floats
        float c = (float)g_cnt[b];
        float inv = (c > 0.f) ? 1.f / c : 0.f;
        if (tid < 128) sp[tid] = g_pool[b * HID + tid] * inv;
        __syncthreads();
        float acc = 0.f;
        #pragma unroll 8
        for (int k = 0; k < 128; k++)
            acc += sp[k] * W3[(size_t)k * OUTD + tid];
        out[b * OUTD + tid] = (c > 0.f) ? (acc + b3[tid]) : 0.f;
    }
}

// ---------------------------------------------------------------------------
extern "C" void kernel_launch(void* const* d_in, const int* in_sizes, int n_in,
                              void* d_out, int out_size) {
    const float* x     = (const float*)d_in[0];
    const int*   ei    = (const int*)d_in[1];      // int32 (JAX x64 disabled)
    const int*   batch = (const int*)d_in[2];
    const float *W1 = (const float*)d_in[3],  *b1 = (const float*)d_in[4];
    const float *W2 = (const float*)d_in[5],  *b2 = (const float*)d_in[6];
    const float *W3 = (const float*)d_in[7],  *b3 = (const float*)d_in[8];
    const float *rW = (const float*)d_in[9],  *rb = (const float*)d_in[10];
    const float *g1 = (const float*)d_in[11], *be1 = (const float*)d_in[12];
    const float *g2 = (const float*)d_in[13], *be2 = (const float*)d_in[14];
    float* out = (float*)d_out;

    int n = in_sizes[0] / 20;
    int e = in_sizes[1] / 2;
    const int* src = ei;
    const int* dst = ei + e;

    mega_kernel<<<NBLK, NTHR>>>(x, src, dst, batch,
                                W1, b1, W2, b2, W3, b3, rW, rb,
                                g1, be1, g2, be2, out, n, e);
}

// round 16
// speedup vs baseline: 1.1618x; 1.1618x over previous
#include <cuda_runtime.h>
#include <cuda_bf16.h>

// ---------------------------------------------------------------------------
// BaseGNN: 3-layer GCN, N=100000, E=1.6M, B=64. Persistent mega-kernel.
// R15 regressed (6 CTAs -> spills). R16: back to 4 CTAs + ALGEBRAIC restructure:
// gathered buffers stored pre-scaled by dinv[src] -> aggregation is a pure
// unweighted sum (1 SHFL/edge, int edge records, FADD, no per-edge norm).
// out[d] = dinv[d] * (h'[d] + sum h'[s]).  bf16 storage, tf32 GEMM,
// 8 even grid barriers (sense self-resets per graph replay).
// ---------------------------------------------------------------------------

#define N_MAX 100000
#define E_MAX 1600000
#define NB    64
#define HID   128
#define OUTD  256
#define NBLK  592
#define NTHR  256
#define NWARP (NBLK * 8)

__device__ int   g_deg[N_MAX];
__device__ int   g_rowptr[N_MAX + 1];
__device__ int   g_cursor[N_MAX];
__device__ int   g_edge[E_MAX];          // src only (rows pre-scaled by dinv)
__device__ __nv_bfloat16 g_bufA[(size_t)N_MAX * HID];
__device__ __nv_bfloat16 g_res [(size_t)N_MAX * HID];
__device__ __nv_bfloat16 g_hbuf[(size_t)N_MAX * HID];
__device__ float g_pool[NB * HID];
__device__ int   g_cnt[NB];
__device__ unsigned g_bar_count = 0;
__device__ unsigned g_bar_sense = 0;

__device__ __forceinline__ void grid_barrier(unsigned& ls) {
    __threadfence();
    __syncthreads();
    ls ^= 1u;
    if (threadIdx.x == 0) {
        unsigned arrived = atomicAdd(&g_bar_count, 1u);
        if (arrived == NBLK - 1u) {
            atomicExch(&g_bar_count, 0u);
            __threadfence();
            atomicExch(&g_bar_sense, ls);
        } else {
            while (((volatile unsigned*)&g_bar_sense)[0] != ls) __nanosleep(64);
            __threadfence();
        }
    }
    __syncthreads();
}

// ---------------------------------------------------------------------------
// L2 residency policy helpers + bf16 packed load/store.
__device__ __forceinline__ unsigned long long mk_policy() {
    unsigned long long p;
    asm("createpolicy.fractional.L2::evict_last.b64 %0, 1.0;" : "=l"(p));
    return p;
}
__device__ __forceinline__ float4 ldg_bf4(const __nv_bfloat16* p, unsigned long long pol) {
    unsigned lo, hi;
    asm volatile("ld.global.L2::cache_hint.v2.u32 {%0,%1}, [%2], %3;"
                 : "=r"(lo), "=r"(hi) : "l"(p), "l"(pol));
    __nv_bfloat162 b0 = *reinterpret_cast<__nv_bfloat162*>(&lo);
    __nv_bfloat162 b1 = *reinterpret_cast<__nv_bfloat162*>(&hi);
    float2 f0 = __bfloat1622float2(b0);
    float2 f1 = __bfloat1622float2(b1);
    return make_float4(f0.x, f0.y, f1.x, f1.y);
}
__device__ __forceinline__ float4 ldg_bf4_plain(const __nv_bfloat16* p) {
    const __nv_bfloat162* q = (const __nv_bfloat162*)p;
    float2 f0 = __bfloat1622float2(q[0]);
    float2 f1 = __bfloat1622float2(q[1]);
    return make_float4(f0.x, f0.y, f1.x, f1.y);
}
__device__ __forceinline__ void stg_bf4(__nv_bfloat16* p, float4 v, unsigned long long pol) {
    __nv_bfloat162 b0 = __floats2bfloat162_rn(v.x, v.y);
    __nv_bfloat162 b1 = __floats2bfloat162_rn(v.z, v.w);
    unsigned lo = *reinterpret_cast<unsigned*>(&b0);
    unsigned hi = *reinterpret_cast<unsigned*>(&b1);
    asm volatile("st.global.L2::cache_hint.v2.u32 [%0], {%1,%2}, %3;"
                 :: "l"(p), "r"(lo), "r"(hi), "l"(pol) : "memory");
}
__device__ __forceinline__ void stg_bf4_plain(__nv_bfloat16* p, float4 v) {
    __nv_bfloat162* q = (__nv_bfloat162*)p;
    q[0] = __floats2bfloat162_rn(v.x, v.y);
    q[1] = __floats2bfloat162_rn(v.z, v.w);
}
__device__ __forceinline__ void stg_bf2(__nv_bfloat16* p, float a, float b, unsigned long long pol) {
    __nv_bfloat162 bb = __floats2bfloat162_rn(a, b);
    unsigned u = *reinterpret_cast<unsigned*>(&bb);
    asm volatile("st.global.L2::cache_hint.b32 [%0], %1, %2;"
                 :: "l"(p), "r"(u), "l"(pol) : "memory");
}

__device__ __forceinline__ void add4(float4& acc, const float4& a) {
    acc.x += a.x; acc.y += a.y; acc.z += a.z; acc.w += a.w;
}
__device__ __forceinline__ void fma4(float4& acc, const float4& a, float w) {
    acc.x += a.x * w; acc.y += a.y * w; acc.z += a.z * w; acc.w += a.w * w;
}

// ---------------------------------------------------------------------------
// Unweighted gather-sum of one node's neighborhood (rows pre-scaled).
__device__ __forceinline__ void gather_body(const __nv_bfloat16* __restrict__ h, int lane,
                                            int rec, int start, int end, float4& acc,
                                            unsigned long long pol) {
    for (int e0 = start; e0 < end; e0 += 32) {
        if (e0 != start) {               // reload for rare deg>32 nodes
            int e = e0 + lane;
            rec = (e < end) ? g_edge[e] : 0;
        }
        int cnt = min(32, end - e0);
        int j = 0;
        for (; j + 8 <= cnt; j += 8) {
            int s[8]; float4 a[8];
            #pragma unroll
            for (int q = 0; q < 8; q++) s[q] = __shfl_sync(0xffffffffu, rec, j + q);
            #pragma unroll
            for (int q = 0; q < 8; q++) a[q] = ldg_bf4(h + (size_t)s[q] * HID + lane * 4, pol);
            #pragma unroll
            for (int q = 0; q < 8; q++) add4(acc, a[q]);
        }
        for (; j + 4 <= cnt; j += 4) {
            int s[4]; float4 a[4];
            #pragma unroll
            for (int q = 0; q < 4; q++) s[q] = __shfl_sync(0xffffffffu, rec, j + q);
            #pragma unroll
            for (int q = 0; q < 4; q++) a[q] = ldg_bf4(h + (size_t)s[q] * HID + lane * 4, pol);
            #pragma unroll
            for (int q = 0; q < 4; q++) add4(acc, a[q]);
        }
        for (; j < cnt; j++) {
            int ss = __shfl_sync(0xffffffffu, rec, j);
            float4 a0 = ldg_bf4(h + (size_t)ss * HID + lane * 4, pol);
            add4(acc, a0);
        }
    }
}

// bias + residual + LN + ReLU epilogue; store scaled (for gather) or plain.
template<bool SCALE_OUT>
__device__ __forceinline__ void ln_store(float4 acc, float4 rr, float dinv,
                                         const float* __restrict__ bias,
                                         const float* __restrict__ gam,
                                         const float* __restrict__ bet,
                                         __nv_bfloat16* __restrict__ outp, int node, int lane,
                                         unsigned long long pol) {
    float4 b4 = ((const float4*)bias)[lane];
    acc.x += rr.x + b4.x; acc.y += rr.y + b4.y;
    acc.z += rr.z + b4.z; acc.w += rr.w + b4.w;
    float s  = acc.x + acc.y + acc.z + acc.w;
    float sq = acc.x*acc.x + acc.y*acc.y + acc.z*acc.z + acc.w*acc.w;
    #pragma unroll
    for (int off = 16; off > 0; off >>= 1) {
        s  += __shfl_xor_sync(0xffffffffu, s,  off);
        sq += __shfl_xor_sync(0xffffffffu, sq, off);
    }
    float mu  = s * (1.f / HID);
    float var = sq * (1.f / HID) - mu * mu;
    float rs  = rsqrtf(var + 1e-5f);
    float4 g4 = ((const float4*)gam)[lane];
    float4 l4 = ((const float4*)bet)[lane];
    float4 o;
    o.x = fmaxf(0.f, (acc.x - mu) * rs * g4.x + l4.x);
    o.y = fmaxf(0.f, (acc.y - mu) * rs * g4.y + l4.y);
    o.z = fmaxf(0.f, (acc.z - mu) * rs * g4.z + l4.z);
    o.w = fmaxf(0.f, (acc.w - mu) * rs * g4.w + l4.w);
    if (SCALE_OUT) {
        o.x *= dinv; o.y *= dinv; o.z *= dinv; o.w *= dinv;
        stg_bf4(outp + (size_t)node * HID + lane * 4, o, pol);
    } else {
        stg_bf4_plain(outp + (size_t)node * HID + lane * 4, o);
    }
}

// Aggregate + LN phase, software-pipelined across strided nodes.
// h rows are pre-scaled; out[d] = dinv[d]*sum. RESID_X: residual = x@rW+rb.
template<bool RESID_X, bool SCALE_OUT>
__device__ void agg_ln_phase(const __nv_bfloat16* __restrict__ h,
                             const float* __restrict__ xsrc,
                             const __nv_bfloat16* __restrict__ rbuf,
                             const float* __restrict__ bias, const float* __restrict__ gam,
                             const float* __restrict__ bet, __nv_bfloat16* __restrict__ outp,
                             int n, int gwarp, int lane, const float* sW,
                             unsigned long long pol) {
    int node = gwarp;
    if (node >= n) return;
    int start = g_rowptr[node], end = g_rowptr[node + 1];
    int rec = (start + lane < end) ? g_edge[start + lane] : 0;
    float4 self = ldg_bf4(h + (size_t)node * HID + lane * 4, pol);
    float xv = 0.f;
    if (RESID_X) xv = (lane < 20) ? xsrc[(size_t)node * 20 + lane] : 0.f;
    while (true) {
        int nxt = node + NWARP;
        bool has = nxt < n;
        int s2 = 0, e2 = 0, rec2 = 0;
        float4 self2 = make_float4(0.f, 0.f, 0.f, 0.f);
        float xv2 = 0.f;
        if (has) {                               // prefetch next node
            s2 = g_rowptr[nxt]; e2 = g_rowptr[nxt + 1];
            rec2 = (s2 + lane < e2) ? g_edge[s2 + lane] : 0;
            self2 = ldg_bf4(h + (size_t)nxt * HID + lane * 4, pol);
            if (RESID_X) xv2 = (lane < 20) ? xsrc[(size_t)nxt * 20 + lane] : 0.f;
        }
        float dinv = rsqrtf((float)(end - start + 1));
        float4 acc = self;                        // self row (already scaled)
        gather_body(h, lane, rec, start, end, acc, pol);
        acc.x *= dinv; acc.y *= dinv; acc.z *= dinv; acc.w *= dinv;
        float4 rr;
        if (RESID_X) {
            rr = ((const float4*)(sW + 20 * 128))[lane];   // rb
            #pragma unroll
            for (int k = 0; k < 20; k++) {
                float xk = __shfl_sync(0xffffffffu, xv, k);
                float4 w = ((const float4*)(sW + k * 128))[lane];
                fma4(rr, w, xk);
            }
        } else {
            rr = ldg_bf4_plain(rbuf + (size_t)node * HID + lane * 4);
        }
        ln_store<SCALE_OUT>(acc, rr, dinv, bias, gam, bet, outp, node, lane, pol);
        if (!has) break;
        node = nxt; start = s2; end = e2; rec = rec2; self = self2; xv = xv2;
    }
}

// ---------------------------------------------------------------------------
// tf32 helpers
__device__ __forceinline__ unsigned f2tf(float f) {
    unsigned r;
    asm("cvt.rna.tf32.f32 %0, %1;" : "=r"(r) : "f"(f));
    return r;
}
__device__ __forceinline__ void mma_tf32(float& d0, float& d1, float& d2, float& d3,
                                         unsigned a0, unsigned a1, unsigned a2, unsigned a3,
                                         unsigned b0, unsigned b1) {
    asm volatile(
        "mma.sync.aligned.m16n8k8.row.col.f32.tf32.tf32.f32 "
        "{%0,%1,%2,%3}, {%4,%5,%6,%7}, {%8,%9}, {%0,%1,%2,%3};\n"
        : "+f"(d0), "+f"(d1), "+f"(d2), "+f"(d3)
        : "r"(a0), "r"(a1), "r"(a2), "r"(a3), "r"(b0), "r"(b1));
}

// GEMM phase: C[n,128] = A_bf16[n,128] @ W[128,128]; output rows scaled by
// dinv[row] (C is the next gather operand), stored bf16 evict_last.
__device__ void gemm_phase128(const __nv_bfloat16* __restrict__ A, const float* __restrict__ W,
                              __nv_bfloat16* __restrict__ C, int n, float* sh,
                              unsigned long long pol) {
    const int rowTiles = (n + 63) >> 6;
    const int ntiles = rowTiles * 2;
    float (*As)[68] = (float(*)[68])sh;              // [32][68] (k-major)
    float (*Ws)[64] = (float(*)[64])(sh + 32 * 68);  // [32][64]
    int tid = threadIdx.x;
    int lane = tid & 31, wid = tid >> 5;
    int wr = (wid & 3) * 16;
    int wc = (wid >> 2) * 32;
    int frow = lane >> 2;
    int fcol = lane & 3;
    for (int t = blockIdx.x; t < ntiles; t += NBLK) {
        int row0 = (t % rowTiles) << 6;
        int col0 = (t / rowTiles) << 6;
        float d[4][4];
        #pragma unroll
        for (int nt = 0; nt < 4; nt++)
            #pragma unroll
            for (int q = 0; q < 4; q++) d[nt][q] = 0.f;
        #pragma unroll
        for (int k0 = 0; k0 < 128; k0 += 32) {
            #pragma unroll
            for (int l = tid; l < 64 * 8; l += NTHR) {
                int m = l >> 3, k4 = l & 7;
                int r = row0 + m;
                float4 v = (r < n) ? ldg_bf4_plain(A + (size_t)r * 128 + k0 + k4 * 4)
                                   : make_float4(0.f, 0.f, 0.f, 0.f);
                As[k4 * 4 + 0][m] = v.x;
                As[k4 * 4 + 1][m] = v.y;
                As[k4 * 4 + 2][m] = v.z;
                As[k4 * 4 + 3][m] = v.w;
            }
            #pragma unroll
            for (int l = tid; l < 32 * 16; l += NTHR) {
                int k = l >> 4, c4 = l & 15;
                float4 v = ((const float4*)(W + (size_t)(k0 + k) * 128 + col0))[c4];
                ((float4*)&Ws[k][c4 * 4])[0] = v;
            }
            __syncthreads();
            #pragma unroll
            for (int kk = 0; kk < 32; kk += 8) {
                int ak = kk + fcol;
                int ar = wr + frow;
                unsigned a0 = f2tf(As[ak    ][ar    ]);
                unsigned a1 = f2tf(As[ak    ][ar + 8]);
                unsigned a2 = f2tf(As[ak + 4][ar    ]);
                unsigned a3 = f2tf(As[ak + 4][ar + 8]);
                #pragma unroll
                for (int nt = 0; nt < 4; nt++) {
                    int bc = wc + nt * 8 + frow;
                    unsigned b0 = f2tf(Ws[ak    ][bc]);
                    unsigned b1 = f2tf(Ws[ak + 4][bc]);
                    mma_tf32(d[nt][0], d[nt][1], d[nt][2], d[nt][3],
                             a0, a1, a2, a3, b0, b1);
                }
            }
            __syncthreads();
        }
        int r = row0 + wr + frow;
        float di0 = (r < n)     ? rsqrtf((float)(g_deg[r] + 1))     : 0.f;
        float di1 = (r + 8 < n) ? rsqrtf((float)(g_deg[r + 8] + 1)) : 0.f;
        #pragma unroll
        for (int nt = 0; nt < 4; nt++) {
            int c = col0 + wc + nt * 8 + fcol * 2;
            if (r < n)     stg_bf2(C + (size_t)r * 128 + c,       d[nt][0] * di0, d[nt][1] * di0, pol);
            if (r + 8 < n) stg_bf2(C + (size_t)(r + 8) * 128 + c, d[nt][2] * di1, d[nt][3] * di1, pol);
        }
    }
}

// ---------------------------------------------------------------------------
__global__ void __launch_bounds__(NTHR, 4) mega_kernel(
    const float* __restrict__ x, const int* __restrict__ src,
    const int* __restrict__ dst, const int* __restrict__ batch,
    const float* __restrict__ W1, const float* __restrict__ b1,
    const float* __restrict__ W2, const float* __restrict__ b2,
    const float* __restrict__ W3, const float* __restrict__ b3,
    const float* __restrict__ rW, const float* __restrict__ rb,
    const float* __restrict__ g1, const float* __restrict__ be1,
    const float* __restrict__ g2, const float* __restrict__ be2,
    float* __restrict__ out, int n, int e)
{
    __shared__ float sh[5248];
    unsigned ls = 0;
    const unsigned long long pol = mk_policy();
    const int tid  = threadIdx.x;
    const int gtid = blockIdx.x * NTHR + tid;
    const int gstr = NBLK * NTHR;
    const int lane = tid & 31, wid = tid >> 5;
    const int gwarp = blockIdx.x * 8 + wid;

    // ---- P0: zero ----
    for (int i = gtid; i < n; i += gstr) g_deg[i] = 0;
    if (gtid < NB) g_cnt[gtid] = 0;
    for (int i = gtid; i < NB * HID; i += gstr) g_pool[i] = 0.f;
    grid_barrier(ls);                                            // B1

    // ---- P1: histograms ----
    for (int i = gtid; i < e; i += gstr) atomicAdd(&g_deg[dst[i]], 1);
    for (int i = gtid; i < n; i += gstr) atomicAdd(&g_cnt[batch[i]], 1);
    grid_barrier(ls);                                            // B2

    // ---- P2: block 0 scans (4 elems/thread); others: W1 GEMM, rows scaled ----
    if (blockIdx.x == 0) {
        int* wsum = (int*)sh;
        int carry = 0;
        for (int base = 0; base < n; base += NTHR * 4) {
            int i0 = base + tid * 4;
            int v0 = (i0 + 0 < n) ? g_deg[i0 + 0] : 0;
            int v1 = (i0 + 1 < n) ? g_deg[i0 + 1] : 0;
            int v2 = (i0 + 2 < n) ? g_deg[i0 + 2] : 0;
            int v3 = (i0 + 3 < n) ? g_deg[i0 + 3] : 0;
            int tsum = v0 + v1 + v2 + v3;
            int xv = tsum;
            #pragma unroll
            for (int off = 1; off < 32; off <<= 1) {
                int t = __shfl_up_sync(0xffffffffu, xv, off);
                if (lane >= off) xv += t;
            }
            if (lane == 31) wsum[wid] = xv;
            __syncthreads();
            if (wid == 0) {
                int sv = (lane < 8) ? wsum[lane] : 0;
                #pragma unroll
                for (int off = 1; off < 8; off <<= 1) {
                    int t = __shfl_up_sync(0xffffffffu, sv, off);
                    if (lane >= off) sv += t;
                }
                if (lane < 8) wsum[lane] = sv;
            }
            __syncthreads();
            int excl = carry + (wid ? wsum[wid - 1] : 0) + xv - tsum;
            if (i0 + 0 < n) { g_rowptr[i0 + 0] = excl;                g_cursor[i0 + 0] = excl; }
            if (i0 + 1 < n) { g_rowptr[i0 + 1] = excl + v0;           g_cursor[i0 + 1] = excl + v0; }
            if (i0 + 2 < n) { g_rowptr[i0 + 2] = excl + v0 + v1;      g_cursor[i0 + 2] = excl + v0 + v1; }
            if (i0 + 3 < n) { g_rowptr[i0 + 3] = excl + v0 + v1 + v2; g_cursor[i0 + 3] = excl + v0 + v1 + v2; }
            int total = wsum[7];
            __syncthreads();
            carry += total;
        }
        if (tid == 0) g_rowptr[n] = carry;
    } else {
        float* sW1 = sh;            // 2560 floats
        for (int i = tid; i < 20 * 128; i += NTHR) sW1[i] = W1[i];
        __syncthreads();
        int w2 = (blockIdx.x - 1) * 8 + wid;
        for (int row = w2; row < n; row += (NBLK - 1) * 8) {
            float xv = (lane < 20) ? x[(size_t)row * 20 + lane] : 0.f;
            float4 a = make_float4(0.f, 0.f, 0.f, 0.f);
            #pragma unroll
            for (int k = 0; k < 20; k++) {
                float xk = __shfl_sync(0xffffffffu, xv, k);
                float4 w = ((const float4*)(sW1 + k * 128))[lane];
                fma4(a, w, xk);
            }
            float dinv = rsqrtf((float)(g_deg[row] + 1));
            a.x *= dinv; a.y *= dinv; a.z *= dinv; a.w *= dinv;
            stg_bf4(g_bufA + (size_t)row * HID + lane * 4, a, pol);
        }
    }
    grid_barrier(ls);                                            // B3

    // ---- P3: csr fill (src only; no norm) ----
    for (int i = gtid; i < e; i += gstr) {
        int s = src[i], d = dst[i];
        int pos = atomicAdd(&g_cursor[d], 1);
        g_edge[pos] = s;
    }
    grid_barrier(ls);                                            // B4

    // ---- layer 1: agg-sum + dinv + (x@rW+rb) residual + LN + ReLU (h1 unscaled) ----
    {
        for (int i = tid; i < 20 * 128; i += NTHR) sh[i] = rW[i];
        if (tid < 128) sh[20 * 128 + tid] = rb[tid];
        __syncthreads();
        agg_ln_phase<true, false>(g_bufA, x, nullptr, b1, g1, be1, g_hbuf, n, gwarp, lane, sh, pol);
    }
    grid_barrier(ls);                                            // B5

    // ---- layer 2 GEMM (tf32, output rows pre-scaled by dinv) ----
    gemm_phase128(g_hbuf, W2, g_bufA, n, sh, pol);
    grid_barrier(ls);                                            // B6

    // ---- layer 2 agg + LN (residual = h1 unscaled; output scaled for agg3) ----
    agg_ln_phase<false, true>(g_bufA, nullptr, g_hbuf, b2, g2, be2, g_res, n, gwarp, lane, nullptr, pol);
    grid_barrier(ls);                                            // B7

    // ---- layer 3: agg-sum + pool fused (contiguous chunks, pipelined) ----
    {
        int ch = (n + NWARP - 1) / NWARP;
        int lo = gwarp * ch;
        int hi = min(n, lo + ch);
        if (lo < hi) {
            float4 pacc = make_float4(0.f, 0.f, 0.f, 0.f);
            int cur = batch[lo];
            int node = lo;
            int start = g_rowptr[node], end = g_rowptr[node + 1];
            int rec = (start + lane < end) ? g_edge[start + lane] : 0;
            float4 self = ldg_bf4(g_res + (size_t)node * HID + lane * 4, pol);
            while (true) {
                int nxt = node + 1;
                bool has = nxt < hi;
                int s2 = 0, e2 = 0, rec2 = 0;
                float4 self2 = make_float4(0.f, 0.f, 0.f, 0.f);
                int gnxt = cur;
                if (has) {
                    s2 = g_rowptr[nxt]; e2 = g_rowptr[nxt + 1];
                    rec2 = (s2 + lane < e2) ? g_edge[s2 + lane] : 0;
                    self2 = ldg_bf4(g_res + (size_t)nxt * HID + lane * 4, pol);
                    gnxt = batch[nxt];
                }
                float dinv = rsqrtf((float)(end - start + 1));
                float4 acc = self;
                gather_body(g_res, lane, rec, start, end, acc, pol);
                pacc.x += acc.x * dinv; pacc.y += acc.y * dinv;
                pacc.z += acc.z * dinv; pacc.w += acc.w * dinv;
                if (!has) break;
                if (gnxt != cur) {
                    float* p = &g_pool[cur * HID + lane * 4];
                    atomicAdd(p + 0, pacc.x); atomicAdd(p + 1, pacc.y);
                    atomicAdd(p + 2, pacc.z); atomicAdd(p + 3, pacc.w);
                    pacc = make_float4(0.f, 0.f, 0.f, 0.f);
                    cur = gnxt;
                }
                node = nxt; start = s2; end = e2; rec = rec2; self = self2;
            }
            float* p = &g_pool[cur * HID + lane * 4];
            atomicAdd(p + 0, pacc.x); atomicAdd(p + 1, pacc.y);
            atomicAdd(p + 2, pacc.z); atomicAdd(p + 3, pacc.w);
        }
    }
    grid_barrier(ls);                                            // B8 (even count)

    // ---- final: out[b,:] = (pool[b,:]/cnt[b]) @ W3 + b3 (blocks 0..63) ----
    if (blockIdx.x < NB) {
        int b = blockIdx.x;
        float* sp = sh;               // 128 floats
        float c = (float)g_cnt[b];
        float inv = (c > 0.f) ? 1.f / c : 0.f;
        if (tid < 128) sp[tid] = g_pool[b * HID + tid] * inv;
        __syncthreads();
        float acc = 0.f;
        #pragma unroll 8
        for (int k = 0; k < 128; k++)
            acc += sp[k] * W3[(size_t)k * OUTD + tid];
        out[b * OUTD + tid] = (c > 0.f) ? (acc + b3[tid]) : 0.f;
    }
}

// ---------------------------------------------------------------------------
extern "C" void kernel_launch(void* const* d_in, const int* in_sizes, int n_in,
                              void* d_out, int out_size) {
    const float* x     = (const float*)d_in[0];
    const int*   ei    = (const int*)d_in[1];      // int32 (JAX x64 disabled)
    const int*   batch = (const int*)d_in[2];
    const float *W1 = (const float*)d_in[3],  *b1 = (const float*)d_in[4];
    const float *W2 = (const float*)d_in[5],  *b2 = (const float*)d_in[6];
    const float *W3 = (const float*)d_in[7],  *b3 = (const float*)d_in[8];
    const float *rW = (const float*)d_in[9],  *rb = (const float*)d_in[10];
    const float *g1 = (const float*)d_in[11], *be1 = (const float*)d_in[12];
    const float *g2 = (const float*)d_in[13], *be2 = (const float*)d_in[14];
    float* out = (float*)d_out;

    int n = in_sizes[0] / 20;
    int e = in_sizes[1] / 2;
    const int* src = ei;
    const int* dst = ei + e;

    mega_kernel<<<NBLK, NTHR>>>(x, src, dst, batch,
                                W1, b1, W2, b2, W3, b3, rW, rb,
                                g1, be1, g2, be2, out, n, e);
}